// round 2
// baseline (speedup 1.0000x reference)
#include <cuda_runtime.h>
#include <cstdint>

// ---------------------------------------------------------------------------
// IWHT3Layer fused kernel, round 2: 256 threads (2 warps/SMSP) to fix the
// exposed-latency problem seen at occ=6.2%/issue=29.5%. Same fused plan:
//   per CTA: 32 pixels, loop t=0..15 { cp.async-staged x/w, f32x2 GEMM },
//   y parked in smem, in-block 2D inverse-WHT butterfly epilogue + bias.
// Per-thread blocking now P=2 pixels x K=4 outputs (acc[2][4] packed over c).
// ---------------------------------------------------------------------------

#define ULL unsigned long long

static constexpr int PIXELS   = 12544;      // 16*28*28
static constexpr int PIX_T    = 32;         // pixels per block
static constexpr int NBLK     = PIXELS / PIX_T;   // 392
static constexpr int T_STRIDE = PIXELS * 64;      // floats per coeff plane
static constexpr int OUT_PER_BRANCH = 16 * 112 * 112 * 64;

static constexpr int THREADS  = 256;

// smem layout (bytes)
static constexpr int Y_BYTES   = PIX_T * 16 * 64 * 4;   // 131072
static constexpr int X_PITCH   = 68 * 4;                // padded row
static constexpr int X_BYTES   = PIX_T * X_PITCH;       // 8704 per buffer
static constexpr int W_BYTES   = 64 * 64 * 4;           // 16384 per buffer
static constexpr int SMEM_BYTES = Y_BYTES + 2 * X_BYTES + 2 * W_BYTES; // 181248

// interleaved-weight scratch: [branch][t][ ((c4*4+kk)*16 + k4)*4 + cc ]
__device__ __align__(16) float g_wT[3][16][4096];

// ---------------- f32x2 helpers ----------------
__device__ __forceinline__ ULL f2fma(ULL a, ULL b, ULL c) {
    ULL d; asm("fma.rn.f32x2 %0, %1, %2, %3;" : "=l"(d) : "l"(a), "l"(b), "l"(c)); return d;
}
__device__ __forceinline__ ULL f2add(ULL a, ULL b) {
    ULL d; asm("add.rn.f32x2 %0, %1, %2;" : "=l"(d) : "l"(a), "l"(b)); return d;
}
__device__ __forceinline__ ULL f2sub(ULL a, ULL b) {   // a - b
    const ULL NEG1 = 0xBF800000BF800000ULL;
    return f2fma(b, NEG1, a);
}
__device__ __forceinline__ ulonglong2 v2add(ulonglong2 a, ulonglong2 b) {
    ulonglong2 r; r.x = f2add(a.x, b.x); r.y = f2add(a.y, b.y); return r;
}
__device__ __forceinline__ ulonglong2 v2sub(ulonglong2 a, ulonglong2 b) {
    ulonglong2 r; r.x = f2sub(a.x, b.x); r.y = f2sub(a.y, b.y); return r;
}
__device__ __forceinline__ float hsum2(ULL a) {
    float lo = __uint_as_float((unsigned)(a & 0xffffffffu));
    float hi = __uint_as_float((unsigned)(a >> 32));
    return lo + hi;
}

// ---------------- cp.async helpers ----------------
__device__ __forceinline__ void cpa16(void* dst_smem, const void* src) {
    unsigned sdst = (unsigned)__cvta_generic_to_shared(dst_smem);
    asm volatile("cp.async.cg.shared.global [%0], [%1], 16;" :: "r"(sdst), "l"(src));
}
#define CP_COMMIT() asm volatile("cp.async.commit_group;")
#define CP_WAIT1()  asm volatile("cp.async.wait_group 1;")

// ---------------- weight interleave kernel ----------------
__global__ void wtrans_kernel(const float* __restrict__ w1,
                              const float* __restrict__ w2,
                              const float* __restrict__ w3) {
    int br = blockIdx.x >> 4;
    int t  = blockIdx.x & 15;
    const float* w = (br == 0 ? w1 : (br == 1 ? w2 : w3)) + t * 4096;
    float* dst = g_wT[br][t];
    for (int idx = threadIdx.x; idx < 4096; idx += blockDim.x) {
        int c = idx >> 6, k = idx & 63;
        int c4 = c >> 2, cc = c & 3, k4 = k >> 2, kk = k & 3;
        dst[((c4 * 4 + kk) * 16 + k4) * 4 + cc] = w[idx];
    }
}

// ---------------- main fused kernel ----------------
__global__ __launch_bounds__(THREADS)
void iwht_kernel(const float* __restrict__ tr1, const float* __restrict__ tr2,
                 const float* __restrict__ tr3,
                 const float* __restrict__ b1, const float* __restrict__ b2,
                 const float* __restrict__ b3,
                 float* __restrict__ out) {
    extern __shared__ char smem[];
    float* ysm  = (float*)smem;                 // [32][16][64]
    char*  xbuf = smem + Y_BYTES;               // 2 x [32][68] floats
    char*  wbuf = smem + Y_BYTES + 2 * X_BYTES; // 2 x interleaved [64][64]

    const int tid  = threadIdx.x;
    const int quad = tid >> 4;          // 0..15 -> 2 pixels each
    const int k4   = tid & 15;          // 0..15 -> 4 k each
    const int pb   = quad * 2;

    const int branch = blockIdx.y;
    const float* tr   = (branch == 0 ? tr1 : (branch == 1 ? tr2 : tr3));
    const float* bias = (branch == 0 ? b1  : (branch == 1 ? b2  : b3));
    const int pix0 = blockIdx.x * PIX_T;
    const float* xg = tr + (size_t)pix0 * 64;
    const float* wg = g_wT[branch][0];

    // stage loader: x tile (32x64, padded rows) + interleaved w_t (16KB)
    auto loadT = [&](int t, int buf) {
        char* xb = xbuf + buf * X_BYTES;
        char* wb = wbuf + buf * W_BYTES;
        const float* xs = xg + (size_t)t * T_STRIDE;
        #pragma unroll
        for (int i = 0; i < 2; i++) {           // 512 chunks of 16B
            int ch = tid + i * THREADS;
            int pix = ch >> 4, seg = ch & 15;
            cpa16(xb + pix * X_PITCH + seg * 16, xs + pix * 64 + seg * 4);
        }
        const float* wsrc = wg + t * 4096;
        #pragma unroll
        for (int i = 0; i < 4; i++) {           // 1024 chunks of 16B
            int ch = tid + i * THREADS;
            cpa16(wb + ch * 16, wsrc + ch * 4);
        }
    };

    loadT(0, 0); CP_COMMIT();
    loadT(1, 1); CP_COMMIT();

    for (int t = 0; t < 16; t++) {
        CP_WAIT1();
        __syncthreads();
        const char* xb = xbuf + (t & 1) * X_BYTES;
        const char* wb = wbuf + (t & 1) * W_BYTES;

        ULL acc[2][4] = {};
        #pragma unroll
        for (int c4 = 0; c4 < 16; c4++) {
            ulonglong2 xv[2], wv[4];
            #pragma unroll
            for (int p = 0; p < 2; p++)
                xv[p] = *(const ulonglong2*)(xb + (pb + p) * X_PITCH + c4 * 16);
            #pragma unroll
            for (int kk = 0; kk < 4; kk++)
                wv[kk] = *(const ulonglong2*)(wb + (((c4 << 2) + kk) << 8) + (k4 << 4));
            #pragma unroll
            for (int p = 0; p < 2; p++)
                #pragma unroll
                for (int kk = 0; kk < 4; kk++) {
                    acc[p][kk] = f2fma(xv[p].x, wv[kk].x, acc[p][kk]);
                    acc[p][kk] = f2fma(xv[p].y, wv[kk].y, acc[p][kk]);
                }
        }
        // reduce packed lanes and park y_t in smem
        #pragma unroll
        for (int p = 0; p < 2; p++) {
            float4 yo;
            yo.x = hsum2(acc[p][0]); yo.y = hsum2(acc[p][1]);
            yo.z = hsum2(acc[p][2]); yo.w = hsum2(acc[p][3]);
            *(float4*)(ysm + ((pb + p) * 16 + t) * 64 + (k4 << 2)) = yo;
        }
        __syncthreads();
        int tn = t + 2;
        if (tn < 16) loadT(tn, t & 1);
        CP_COMMIT();                            // empty tail groups keep counts aligned
    }

    __syncthreads();

    // ---------------- epilogue: 2D inverse WHT + bias + store ----------------
    const ULL SC = 0x3D8000003D800000ULL;       // (1/16, 1/16)
    float* outB = out + (size_t)branch * OUT_PER_BRANCH;

    #pragma unroll
    for (int it = 0; it < 2; it++) {
        int unit = it * THREADS + tid;
        int pix = unit >> 4, kq = unit & 15;

        ulonglong2 Y[16];
        #pragma unroll
        for (int t = 0; t < 16; t++)
            Y[t] = *(const ulonglong2*)(ysm + (pix * 16 + t) * 64 + (kq << 2));

        // u-stage: U[p][v] = sum_u H[p][u] Y[4u+v]
        ulonglong2 U[4][4];
        #pragma unroll
        for (int v = 0; v < 4; v++) {
            ulonglong2 s0 = v2add(Y[v],     Y[8 + v]);
            ulonglong2 s1 = v2add(Y[4 + v], Y[12 + v]);
            ulonglong2 d0 = v2sub(Y[v],     Y[8 + v]);
            ulonglong2 d1 = v2sub(Y[4 + v], Y[12 + v]);
            U[0][v] = v2add(s0, s1); U[1][v] = v2sub(s0, s1);
            U[2][v] = v2add(d0, d1); U[3][v] = v2sub(d0, d1);
        }

        int P = pix0 + pix;
        int b = P / 784, r = P % 784;
        int i = r / 28, j = r % 28;
        ulonglong2 bb = *(const ulonglong2*)(bias + (kq << 2));
        float* o0 = outB + ((size_t)(b * 112 + i * 4) * 112 + j * 4) * 64 + (kq << 2);

        #pragma unroll
        for (int p = 0; p < 4; p++) {
            ulonglong2 s0 = v2add(U[p][0], U[p][2]);
            ulonglong2 s1 = v2add(U[p][1], U[p][3]);
            ulonglong2 d0 = v2sub(U[p][0], U[p][2]);
            ulonglong2 d1 = v2sub(U[p][1], U[p][3]);
            ulonglong2 Z[4];
            Z[0] = v2add(s0, s1); Z[1] = v2sub(s0, s1);
            Z[2] = v2add(d0, d1); Z[3] = v2sub(d0, d1);
            float* orow = o0 + p * 112 * 64;
            #pragma unroll
            for (int q = 0; q < 4; q++) {
                ulonglong2 o;
                o.x = f2fma(Z[q].x, SC, bb.x);
                o.y = f2fma(Z[q].y, SC, bb.y);
                *(ulonglong2*)(orow + q * 64) = o;
            }
        }
    }
}

// ---------------- launch ----------------
extern "C" void kernel_launch(void* const* d_in, const int* in_sizes, int n_in,
                              void* d_out, int out_size) {
    (void)in_sizes; (void)n_in; (void)out_size;
    const float* tr1 = (const float*)d_in[0];
    const float* tr2 = (const float*)d_in[1];
    const float* tr3 = (const float*)d_in[2];
    const float* w1  = (const float*)d_in[3];
    const float* w2  = (const float*)d_in[4];
    const float* w3  = (const float*)d_in[5];
    const float* b1  = (const float*)d_in[6];
    const float* b2  = (const float*)d_in[7];
    const float* b3  = (const float*)d_in[8];
    float* out = (float*)d_out;

    cudaFuncSetAttribute(iwht_kernel, cudaFuncAttributeMaxDynamicSharedMemorySize,
                         SMEM_BYTES);

    wtrans_kernel<<<48, 256>>>(w1, w2, w3);
    dim3 grid(NBLK, 3);
    iwht_kernel<<<grid, THREADS, SMEM_BYTES>>>(tr1, tr2, tr3, b1, b2, b3, out);
}

// round 4
// speedup vs baseline: 1.9508x; 1.9508x over previous
#include <cuda_runtime.h>
#include <cuda_bf16.h>
#include <cstdint>

// ---------------------------------------------------------------------------
// IWHT3Layer, round 4: warp-level mma.sync (bf16 3-term split, baseline PTX —
// no 'a'-features) + all-t-in-registers WHT epilogue.
//   CTA: 32 pixels x 64 k x 1 branch, 256 threads (8 warps).
//   Warp w: m16 block (w&1) x n16 block (w>>2? no: w>>1), ALL 16 t.
//   acc y[t][nbq][4] = 128 regs/thread -> butterflies fully in registers.
//   A: x f32 -> bf16 hi/lo, smem pitch-144B (conflict-free ldmatrix + STS),
//      double-buffered, prefetch t+1 during t's MMAs.
//   B: pre-fragmented per-lane in gmem by wprep (LDG.64, L2-resident, no smem).
// ---------------------------------------------------------------------------

#define U32 unsigned int
#define U64 unsigned long long

static constexpr int PIXELS   = 12544;
static constexpr int PIX_CTA  = 32;
static constexpr int NBLK     = PIXELS / PIX_CTA;   // 392
static constexpr int T_STRIDE = PIXELS * 64;
static constexpr long long OPB = 16LL * 112 * 112 * 64;

// A smem: 2 buffers x (hi 32x144B + lo 32x144B)
static constexpr int A_PITCH  = 144;                 // 72 bf16
static constexpr int A_HALF   = 32 * A_PITCH;        // 4608
static constexpr int A_BUF    = 2 * A_HALF;          // 9216

// B fragments: [branch][t][kc4][nb8][term2][lane32][reg2] u32
__device__ __align__(16) U32 g_bfrag[3 * 16 * 4096];

// ---------------- helpers ----------------
__device__ __forceinline__ U32 smem_u32(const void* p) {
    U32 a; asm("{ .reg .u64 t; cvta.to.shared.u64 t, %1; cvt.u32.u64 %0, t; }"
               : "=r"(a) : "l"(p)); return a;
}
__device__ __forceinline__ U32 packbf(float lo, float hi) {   // mem order [lo,hi]
    U32 d; asm("cvt.rn.bf16x2.f32 %0, %1, %2;" : "=r"(d) : "f"(hi), "f"(lo));
    return d;
}
__device__ __forceinline__ float bflo_f(U32 h) { return __uint_as_float(h << 16); }
__device__ __forceinline__ float bfhi_f(U32 h) { return __uint_as_float(h & 0xffff0000u); }

__device__ __forceinline__ void ldm4(U32& a0, U32& a1, U32& a2, U32& a3, U32 addr) {
    asm volatile("ldmatrix.sync.aligned.m8n8.x4.shared.b16 {%0,%1,%2,%3}, [%4];"
                 : "=r"(a0), "=r"(a1), "=r"(a2), "=r"(a3) : "r"(addr));
}
__device__ __forceinline__ void mma16816(float* d, U32 a0, U32 a1, U32 a2, U32 a3,
                                         U32 b0, U32 b1) {
    asm volatile("mma.sync.aligned.m16n8k16.row.col.f32.bf16.bf16.f32 "
                 "{%0,%1,%2,%3}, {%4,%5,%6,%7}, {%8,%9}, {%0,%1,%2,%3};"
                 : "+f"(d[0]), "+f"(d[1]), "+f"(d[2]), "+f"(d[3])
                 : "r"(a0), "r"(a1), "r"(a2), "r"(a3), "r"(b0), "r"(b1));
}

struct F2 { float x, y; };
__device__ __forceinline__ F2 f2add(F2 a, F2 b) { return {a.x + b.x, a.y + b.y}; }
__device__ __forceinline__ F2 f2sub(F2 a, F2 b) { return {a.x - b.x, a.y - b.y}; }

// ---------------- prep: build B fragments (one-time, tiny) ----------------
__global__ void wprep_kernel(const float* __restrict__ w1,
                             const float* __restrict__ w2,
                             const float* __restrict__ w3) {
    int br = blockIdx.x >> 4, t = blockIdx.x & 15;
    const float* w = (br == 0 ? w1 : (br == 1 ? w2 : w3)) + t * 4096;
    __nv_bfloat16* frag = (__nv_bfloat16*)(g_bfrag + (br * 16 + t) * 4096);
    for (int idx = threadIdx.x; idx < 4096; idx += blockDim.x) {
        int c = idx >> 6, k = idx & 63;          // w[c][k], coalesced over k
        float v = w[idx];
        __nv_bfloat16 hi = __float2bfloat16(v);
        __nv_bfloat16 lo = __float2bfloat16(v - __bfloat162float(hi));
        // B frag (k16 x n8, col-major): lane l: b0 = {B[2(l%4)][l/4], B[2(l%4)+1][l/4]}, b1: +8
        int kc = c >> 4, cw = c & 15;
        int regj = cw >> 3, l4 = (cw & 7) >> 1, half = cw & 1;
        int nb = k >> 3, lane = (k & 7) * 4 + l4;
        int u0 = (((kc * 8 + nb) * 2 + 0) * 32 + lane) * 2 + regj;   // hi term
        int u1 = (((kc * 8 + nb) * 2 + 1) * 32 + lane) * 2 + regj;   // lo term
        frag[u0 * 2 + half] = hi;
        frag[u1 * 2 + half] = lo;
    }
}

// ---------------- main kernel ----------------
__global__ __launch_bounds__(256, 1)
void iwht_mma_kernel(const float* __restrict__ tr1, const float* __restrict__ tr2,
                     const float* __restrict__ tr3,
                     const float* __restrict__ b1, const float* __restrict__ b2,
                     const float* __restrict__ b3,
                     float* __restrict__ out) {
    __shared__ __align__(16) char asm_buf[2 * A_BUF];   // 18432 B

    const int tid  = threadIdx.x;
    const int lane = tid & 31;
    const int w    = tid >> 5;
    const int mb   = w & 1;        // m16 block
    const int nb2  = w >> 1;       // n16 block (k 16*nb2 .. +15)

    const int branch = blockIdx.y;
    const float* tr   = (branch == 0 ? tr1 : (branch == 1 ? tr2 : tr3));
    const float* bias = (branch == 0 ? b1  : (branch == 1 ? b2  : b3));
    const int pix0 = blockIdx.x * PIX_CTA;

    // conversion role: thread -> (row 0..31, seg 0..7 of 8 floats)
    const int crow = tid >> 3, cseg = tid & 7;
    const float* xrow = tr + (size_t)(pix0 + crow) * 64 + cseg * 8;
    char* const abuf = asm_buf;

    auto cvtStore = [&](float4 a, float4 b, int buf) {
        U32 h0 = packbf(a.x, a.y), h1 = packbf(a.z, a.w);
        U32 h2 = packbf(b.x, b.y), h3 = packbf(b.z, b.w);
        U32 l0 = packbf(a.x - bflo_f(h0), a.y - bfhi_f(h0));
        U32 l1 = packbf(a.z - bflo_f(h1), a.w - bfhi_f(h1));
        U32 l2 = packbf(b.x - bflo_f(h2), b.y - bfhi_f(h2));
        U32 l3 = packbf(b.z - bflo_f(h3), b.w - bfhi_f(h3));
        int off = buf * A_BUF + crow * A_PITCH + cseg * 16;
        *(uint4*)(abuf + off)          = make_uint4(h0, h1, h2, h3);
        *(uint4*)(abuf + off + A_HALF) = make_uint4(l0, l1, l2, l3);
    };

    // prologue: stage t=0
    {
        float4 a = *(const float4*)(xrow);
        float4 b = *(const float4*)(xrow + 4);
        cvtStore(a, b, 0);
    }
    __syncthreads();

    // ldmatrix base address for this warp (A hi; lo at +A_HALF)
    const U32 sbase = smem_u32(asm_buf);
    const U32 arow0 = sbase + (U32)((mb * 16 + (lane & 15)) * A_PITCH + (lane >> 4) * 16);

    float acc[16][2][4];
    #pragma unroll
    for (int t = 0; t < 16; t++)
        #pragma unroll
        for (int q = 0; q < 2; q++)
            #pragma unroll
            for (int i = 0; i < 4; i++) acc[t][q][i] = 0.0f;

    #pragma unroll
    for (int t = 0; t < 16; t++) {
        // B fragments for this t (L2-hot LDG.64)
        const U32* gb = g_bfrag + (branch * 16 + t) * 4096;
        U64 bfr[4][2][2];
        #pragma unroll
        for (int kc = 0; kc < 4; kc++)
            #pragma unroll
            for (int nq = 0; nq < 2; nq++)
                #pragma unroll
                for (int tm = 0; tm < 2; tm++)
                    bfr[kc][nq][tm] = *(const U64*)(gb +
                        ((((kc * 8 + (nb2 * 2 + nq)) * 2 + tm) * 32 + lane) * 2));

        // prefetch x for t+1
        float4 pa, pb;
        if (t < 15) {
            const float* xs = xrow + (size_t)(t + 1) * T_STRIDE;
            pa = *(const float4*)(xs);
            pb = *(const float4*)(xs + 4);
        }

        // MMAs for t
        const U32 ab = arow0 + (U32)((t & 1) * A_BUF);
        #pragma unroll
        for (int kc = 0; kc < 4; kc++) {
            U32 ah0, ah1, ah2, ah3, al0, al1, al2, al3;
            ldm4(ah0, ah1, ah2, ah3, ab + kc * 32);
            ldm4(al0, al1, al2, al3, ab + kc * 32 + A_HALF);
            #pragma unroll
            for (int nq = 0; nq < 2; nq++) {
                U32 bh0 = (U32)(bfr[kc][nq][0]), bh1 = (U32)(bfr[kc][nq][0] >> 32);
                U32 bl0 = (U32)(bfr[kc][nq][1]), bl1 = (U32)(bfr[kc][nq][1] >> 32);
                mma16816(acc[t][nq], ah0, ah1, ah2, ah3, bh0, bh1);   // hi*hi
                mma16816(acc[t][nq], ah0, ah1, ah2, ah3, bl0, bl1);   // hi*lo
                mma16816(acc[t][nq], al0, al1, al2, al3, bh0, bh1);   // lo*hi
            }
        }

        // stage t+1
        if (t < 15) cvtStore(pa, pb, (t + 1) & 1);
        __syncthreads();
    }

    // ---------------- epilogue: in-register 2D WHT + bias + stores ----------
    const int cl = lane & 3, rl = lane >> 2;
    float* outB = out + (size_t)branch * OPB;

    float2 bv[2];
    #pragma unroll
    for (int nq = 0; nq < 2; nq++)
        bv[nq] = *(const float2*)(bias + nb2 * 16 + nq * 8 + cl * 2);

    const int kst = nb2 * 16 + cl * 2;       // + nq*8; valid float4 base on even lanes

    #pragma unroll
    for (int rh = 0; rh < 2; rh++) {
        const int P = pix0 + mb * 16 + rh * 8 + rl;
        const int pb_ = P / 784, rr = P - pb_ * 784;
        const int ii = rr / 28, jj = rr - ii * 28;
        float* obase = outB + ((size_t)(pb_ * 112 + ii * 4) * 112 + jj * 4) * 64;

        #pragma unroll
        for (int nq = 0; nq < 2; nq++) {
            // u-stage butterflies over t = 4u+v
            F2 U[4][4];
            #pragma unroll
            for (int v = 0; v < 4; v++) {
                F2 y0 = {acc[v][nq][rh * 2],      acc[v][nq][rh * 2 + 1]};
                F2 y1 = {acc[4 + v][nq][rh * 2],  acc[4 + v][nq][rh * 2 + 1]};
                F2 y2 = {acc[8 + v][nq][rh * 2],  acc[8 + v][nq][rh * 2 + 1]};
                F2 y3 = {acc[12 + v][nq][rh * 2], acc[12 + v][nq][rh * 2 + 1]};
                F2 s0 = f2add(y0, y2), s1 = f2add(y1, y3);
                F2 d0 = f2sub(y0, y2), d1 = f2sub(y1, y3);
                U[0][v] = f2add(s0, s1); U[1][v] = f2sub(s0, s1);
                U[2][v] = f2add(d0, d1); U[3][v] = f2sub(d0, d1);
            }
            #pragma unroll
            for (int p = 0; p < 4; p++) {
                F2 s0 = f2add(U[p][0], U[p][2]), s1 = f2add(U[p][1], U[p][3]);
                F2 d0 = f2sub(U[p][0], U[p][2]), d1 = f2sub(U[p][1], U[p][3]);
                F2 Z[4];
                Z[0] = f2add(s0, s1); Z[1] = f2sub(s0, s1);
                Z[2] = f2add(d0, d1); Z[3] = f2sub(d0, d1);
                float* orow = obase + (size_t)p * 7168 + nq * 8 + kst;  // 112*64
                #pragma unroll
                for (int q = 0; q < 4; q++) {
                    float zx = fmaf(Z[q].x, 0.0625f, bv[nq].x);
                    float zy = fmaf(Z[q].y, 0.0625f, bv[nq].y);
                    float wx = __shfl_xor_sync(0xffffffffu, zx, 1);
                    float wy = __shfl_xor_sync(0xffffffffu, zy, 1);
                    if (!(lane & 1))
                        *(float4*)(orow + q * 64) = make_float4(zx, zy, wx, wy);
                }
            }
        }
    }
}

// ---------------- launch ----------------
extern "C" void kernel_launch(void* const* d_in, const int* in_sizes, int n_in,
                              void* d_out, int out_size) {
    (void)in_sizes; (void)n_in; (void)out_size;
    const float* tr1 = (const float*)d_in[0];
    const float* tr2 = (const float*)d_in[1];
    const float* tr3 = (const float*)d_in[2];
    const float* w1  = (const float*)d_in[3];
    const float* w2  = (const float*)d_in[4];
    const float* w3  = (const float*)d_in[5];
    const float* b1  = (const float*)d_in[6];
    const float* b2  = (const float*)d_in[7];
    const float* b3  = (const float*)d_in[8];
    float* out = (float*)d_out;

    wprep_kernel<<<48, 256>>>(w1, w2, w3);
    dim3 grid(NBLK, 3);
    iwht_mma_kernel<<<grid, 256>>>(tr1, tr2, tr3, b1, b2, b3, out);
}

// round 5
// speedup vs baseline: 2.4292x; 1.2453x over previous
#include <cuda_runtime.h>
#include <cuda_fp16.h>
#include <cstdint>

// ---------------------------------------------------------------------------
// IWHT3Layer, round 5: single-pass fp16 mma.sync (m16n8k16, baseline PTX),
// 512 threads / 16 warps (tile m16 x n8), all-t-in-register WHT epilogue.
//   A: x f32 LDG (prefetch t+1) -> f16 -> smem pitch-144B, double-buffered.
//   B: pre-fragmented fp16 per-lane in gmem (L2-hot), register double-buffer.
//   acc y[16t][4] = 64 regs/thread -> 2D WHT butterflies fully in registers.
// ---------------------------------------------------------------------------

#define U32 unsigned int
#define U64 unsigned long long

static constexpr int PIXELS   = 12544;
static constexpr int PIX_CTA  = 32;
static constexpr int NBLK     = PIXELS / PIX_CTA;   // 392
static constexpr int T_STRIDE = PIXELS * 64;
static constexpr long long OPB = 16LL * 112 * 112 * 64;

static constexpr int A_PITCH  = 144;                 // conflict-free ldmatrix+STS
static constexpr int A_BUF    = 32 * A_PITCH;        // 4608 B per buffer

// B fragments: U64[(((br*16+t)*4+kc)*8+nb)*32 + lane]
__device__ __align__(16) U64 g_bfrag[3 * 16 * 4 * 8 * 32];

// ---------------- helpers ----------------
__device__ __forceinline__ U32 smem_u32(const void* p) {
    U32 a; asm("{ .reg .u64 t; cvta.to.shared.u64 t, %1; cvt.u32.u64 %0, t; }"
               : "=r"(a) : "l"(p)); return a;
}
__device__ __forceinline__ void ldm4(U32& a0, U32& a1, U32& a2, U32& a3, U32 addr) {
    asm volatile("ldmatrix.sync.aligned.m8n8.x4.shared.b16 {%0,%1,%2,%3}, [%4];"
                 : "=r"(a0), "=r"(a1), "=r"(a2), "=r"(a3) : "r"(addr));
}
__device__ __forceinline__ void mma16816(float* d, U32 a0, U32 a1, U32 a2, U32 a3,
                                         U32 b0, U32 b1) {
    asm volatile("mma.sync.aligned.m16n8k16.row.col.f32.f16.f16.f32 "
                 "{%0,%1,%2,%3}, {%4,%5,%6,%7}, {%8,%9}, {%0,%1,%2,%3};"
                 : "+f"(d[0]), "+f"(d[1]), "+f"(d[2]), "+f"(d[3])
                 : "r"(a0), "r"(a1), "r"(a2), "r"(a3), "r"(b0), "r"(b1));
}
struct F2 { float x, y; };
__device__ __forceinline__ F2 f2add(F2 a, F2 b) { return {a.x + b.x, a.y + b.y}; }
__device__ __forceinline__ F2 f2sub(F2 a, F2 b) { return {a.x - b.x, a.y - b.y}; }

// ---------------- prep: build fp16 B fragments (one-time) ----------------
__global__ void wprep_kernel(const float* __restrict__ w1,
                             const float* __restrict__ w2,
                             const float* __restrict__ w3) {
    int br = blockIdx.x >> 4, t = blockIdx.x & 15;
    const float* w = (br == 0 ? w1 : (br == 1 ? w2 : w3)) + t * 4096;
    __half* frag = (__half*)(g_bfrag + (br * 16 + t) * 4 * 8 * 32);
    for (int idx = threadIdx.x; idx < 4096; idx += blockDim.x) {
        int c = idx >> 6, k = idx & 63;          // w[c][k], coalesced over k
        __half h = __float2half(w[idx]);
        int kc = c >> 4, cw = c & 15;
        int nb = k >> 3, lane = (k & 7) * 4 + ((cw & 7) >> 1);
        int regj = cw >> 3, half = cw & 1;
        frag[(((kc * 8 + nb) * 32 + lane) * 2 + regj) * 2 + half] = h;
    }
}

// ---------------- main kernel ----------------
__global__ __launch_bounds__(512, 1)
void iwht_mma_kernel(const float* __restrict__ tr1, const float* __restrict__ tr2,
                     const float* __restrict__ tr3,
                     const float* __restrict__ b1, const float* __restrict__ b2,
                     const float* __restrict__ b3,
                     float* __restrict__ out) {
    __shared__ __align__(16) char asm_buf[2 * A_BUF];   // 9216 B

    const int tid  = threadIdx.x;
    const int lane = tid & 31;
    const int w    = tid >> 5;     // 0..15
    const int mb   = w & 1;        // m16 block (pixels)
    const int nb   = w >> 1;       // n8 block (k outputs)

    const int branch = blockIdx.y;
    const float* tr   = (branch == 0 ? tr1 : (branch == 1 ? tr2 : tr3));
    const float* bias = (branch == 0 ? b1  : (branch == 1 ? b2  : b3));
    const int pix0 = blockIdx.x * PIX_CTA;

    // conversion role: thread -> (row 0..31, 4 floats at cseg*4)
    const int crow = tid >> 4, cseg = tid & 15;
    const float* xrow = tr + (size_t)(pix0 + crow) * 64 + cseg * 4;

    auto cvtStore = [&](float4 a, int buf) {
        __half2 h0 = __floats2half2_rn(a.x, a.y);
        __half2 h1 = __floats2half2_rn(a.z, a.w);
        U32 u0 = *reinterpret_cast<U32*>(&h0);
        U32 u1 = *reinterpret_cast<U32*>(&h1);
        *(uint2*)(asm_buf + buf * A_BUF + crow * A_PITCH + cseg * 8) =
            make_uint2(u0, u1);
    };

    // B fragment pointer for this warp (U64 per (t, kc))
    const U64* gb = g_bfrag + ((size_t)branch * 16 * 4 * 8 + nb) * 32 + lane;
    auto loadB = [&](int t, U64* dst) {
        #pragma unroll
        for (int kc = 0; kc < 4; kc++)
            dst[kc] = gb[((t * 4 + kc) * 8) * 32];
    };

    // prologue: stage t=0
    cvtStore(*(const float4*)xrow, 0);
    U64 bcur[4], bnxt[4];
    loadB(0, bcur);
    __syncthreads();

    const U32 sbase = smem_u32(asm_buf);
    const U32 arow0 = sbase + (U32)((mb * 16 + (lane & 15)) * A_PITCH + (lane >> 4) * 16);

    float acc[16][4];
    #pragma unroll
    for (int t = 0; t < 16; t++)
        #pragma unroll
        for (int i = 0; i < 4; i++) acc[t][i] = 0.0f;

    #pragma unroll
    for (int t = 0; t < 16; t++) {
        // prefetch x(t+1) and B(t+1)
        float4 pa;
        if (t < 15) {
            pa = *(const float4*)(xrow + (size_t)(t + 1) * T_STRIDE);
            loadB(t + 1, bnxt);
        }

        // MMAs for t
        const U32 ab = arow0 + (U32)((t & 1) * A_BUF);
        #pragma unroll
        for (int kc = 0; kc < 4; kc++) {
            U32 a0, a1, a2, a3;
            ldm4(a0, a1, a2, a3, ab + kc * 32);
            mma16816(acc[t], a0, a1, a2, a3,
                     (U32)bcur[kc], (U32)(bcur[kc] >> 32));
        }

        if (t < 15) {
            cvtStore(pa, (t + 1) & 1);
            #pragma unroll
            for (int kc = 0; kc < 4; kc++) bcur[kc] = bnxt[kc];
        }
        __syncthreads();
    }

    // ---------------- epilogue: in-register 2D WHT + bias + stores ----------
    const int cl = lane & 3, rl = lane >> 2;
    float* outB = out + (size_t)branch * OPB;
    const int kst = nb * 8 + cl * 2;
    const float2 bv = *(const float2*)(bias + kst);

    #pragma unroll
    for (int rh = 0; rh < 2; rh++) {
        const int P = pix0 + mb * 16 + rh * 8 + rl;
        const int pb_ = P / 784, rr = P - pb_ * 784;
        const int ii = rr / 28, jj = rr - ii * 28;
        float* obase = outB + ((size_t)(pb_ * 112 + ii * 4) * 112 + jj * 4) * 64;

        // u-stage butterflies over t = 4u+v
        F2 U[4][4];
        #pragma unroll
        for (int v = 0; v < 4; v++) {
            F2 y0 = {acc[v][rh * 2],      acc[v][rh * 2 + 1]};
            F2 y1 = {acc[4 + v][rh * 2],  acc[4 + v][rh * 2 + 1]};
            F2 y2 = {acc[8 + v][rh * 2],  acc[8 + v][rh * 2 + 1]};
            F2 y3 = {acc[12 + v][rh * 2], acc[12 + v][rh * 2 + 1]};
            F2 s0 = f2add(y0, y2), s1 = f2add(y1, y3);
            F2 d0 = f2sub(y0, y2), d1 = f2sub(y1, y3);
            U[0][v] = f2add(s0, s1); U[1][v] = f2sub(s0, s1);
            U[2][v] = f2add(d0, d1); U[3][v] = f2sub(d0, d1);
        }
        #pragma unroll
        for (int p = 0; p < 4; p++) {
            F2 s0 = f2add(U[p][0], U[p][2]), s1 = f2add(U[p][1], U[p][3]);
            F2 d0 = f2sub(U[p][0], U[p][2]), d1 = f2sub(U[p][1], U[p][3]);
            F2 Z[4];
            Z[0] = f2add(s0, s1); Z[1] = f2sub(s0, s1);
            Z[2] = f2add(d0, d1); Z[3] = f2sub(d0, d1);
            float* orow = obase + (size_t)p * 7168 + kst;    // 112*64
            #pragma unroll
            for (int q = 0; q < 4; q++) {
                float zx = fmaf(Z[q].x, 0.0625f, bv.x);
                float zy = fmaf(Z[q].y, 0.0625f, bv.y);
                float wx = __shfl_xor_sync(0xffffffffu, zx, 1);
                float wy = __shfl_xor_sync(0xffffffffu, zy, 1);
                if (!(lane & 1))
                    *(float4*)(orow + q * 64) = make_float4(zx, zy, wx, wy);
            }
        }
    }
}

// ---------------- launch ----------------
extern "C" void kernel_launch(void* const* d_in, const int* in_sizes, int n_in,
                              void* d_out, int out_size) {
    (void)in_sizes; (void)n_in; (void)out_size;
    const float* tr1 = (const float*)d_in[0];
    const float* tr2 = (const float*)d_in[1];
    const float* tr3 = (const float*)d_in[2];
    const float* w1  = (const float*)d_in[3];
    const float* w2  = (const float*)d_in[4];
    const float* w3  = (const float*)d_in[5];
    const float* b1  = (const float*)d_in[6];
    const float* b2  = (const float*)d_in[7];
    const float* b3  = (const float*)d_in[8];
    float* out = (float*)d_out;

    wprep_kernel<<<48, 256>>>(w1, w2, w3);
    dim3 grid(NBLK, 3);
    iwht_mma_kernel<<<grid, 512>>>(tr1, tr2, tr3, b1, b2, b3, out);
}